// round 15
// baseline (speedup 1.0000x reference)
#include <cuda_runtime.h>
#include <math.h>

#define IMG   512
#define PIX   (IMG * IMG)
#define NIMG  64
#define TX    128
#define RPB   64
#define NITER (RPB + 10)            // 74 streamed rows per block
#define NPAIR (NITER / 2)           // 37 row pairs
#define WCOLS 42                    // 32 main + 10 halo columns
#define NSTG  4                     // cp.async pipeline stages
#define GX    (IMG / TX)            // 4
#define GY    (IMG / RPB)           // 8
#define GZ    (NIMG / 2)            // 32 image pairs (f32x2 packing)
#define NBLK  (GX * GY * GZ)        // 1024

typedef unsigned long long u64;

__device__ double g_part[NBLK];
__device__ int    g_cnt;            // zero-initialized; self-resets each launch

static __device__ __forceinline__ u64 pk2(float a, float b) {
    u64 r; asm("mov.b64 %0, {%1, %2};" : "=l"(r) : "f"(a), "f"(b)); return r;
}
static __device__ __forceinline__ void unpk2(u64 v, float& a, float& b) {
    asm("mov.b64 {%0, %1}, %2;" : "=f"(a), "=f"(b) : "l"(v));
}
static __device__ __forceinline__ u64 f2add(u64 a, u64 b) {
    u64 d; asm("add.rn.f32x2 %0, %1, %2;" : "=l"(d) : "l"(a), "l"(b)); return d;
}
static __device__ __forceinline__ u64 f2mul(u64 a, u64 b) {
    u64 d; asm("mul.rn.f32x2 %0, %1, %2;" : "=l"(d) : "l"(a), "l"(b)); return d;
}
static __device__ __forceinline__ u64 f2fma(u64 a, u64 b, u64 c) {
    u64 d; asm("fma.rn.f32x2 %0, %1, %2, %3;" : "=l"(d) : "l"(a), "l"(b), "l"(c)); return d;
}

// 4-byte async copy with zero-fill when sz==0 (OOB padding)
#define CPA(DST, SRC, SZ) \
    asm volatile("cp.async.ca.shared.global [%0], [%1], 4, %2;" \
                 :: "r"(DST), "l"(SRC), "r"(SZ) : "memory")
#define CP_COMMIT() asm volatile("cp.async.commit_group;" ::: "memory")
#define CP_WAIT2()  asm volatile("cp.async.wait_group 2;" ::: "memory")

__global__ void __launch_bounds__(TX, 3) ssim_main(
    const float* __restrict__ pred, const float* __restrict__ gt,
    float* __restrict__ out)
{
    // R9/R13 warp-private pipeline with cp.async ingest:
    //  - gmem -> smem copies bypass registers (frees the 16 prefetch regs)
    //  - 4-stage pipeline (~3 pairs of DRAM cover) at zero register cost
    //  - raw (p0,p1,g0,g1) tile; hblur computes P,G,S,X per tap (R9 form)
    __shared__ float4 sw[TX / 32][NSTG][2][WCOLS];  // [warp][stage][row][col]
    __shared__ float wred[TX / 32];
    __shared__ int   slast;

    const int tid  = threadIdx.x;
    const int wpid = tid >> 5;
    const int lane = tid & 31;
    const int cx   = blockIdx.x * TX + wpid * 32;   // warp's first output col
    const int ry0  = blockIdx.y * RPB;
    const int im0  = blockIdx.z;

    const float* p0 = pred + (size_t)im0 * PIX;
    const float* p1 = pred + (size_t)(im0 + NIMG / 2) * PIX;
    const float* g0 = gt   + (size_t)im0 * PIX;
    const float* g1 = gt   + (size_t)(im0 + NIMG / 2) * PIX;

    // Gaussian 1D weights (sigma = 11/6, normalized) — same math as reference
    float w[6];
    {
        const float sig = 11.0f / 6.0f;
        const float inv = 1.0f / (2.0f * sig * sig);
        float e[6];
        #pragma unroll
        for (int d = 0; d < 6; ++d) e[d] = expf(-(float)(d * d) * inv);
        float s = e[0] + 2.f * (e[1] + e[2] + e[3] + e[4] + e[5]);
        #pragma unroll
        for (int d = 0; d < 6; ++d) w[d] = e[d] / s;
    }
    u64 w2[6];
    #pragma unroll
    for (int d = 0; d < 6; ++d) w2[d] = pk2(w[d], w[d]);

    const float C1 = 0.01f * 0.01f;
    const float C2 = 0.03f * 0.03f;
    const u64 c1_2  = pk2(C1, C1);
    const u64 c2_2  = pk2(C2, C2);
    const u64 c12_2 = pk2(C1 + C2, C1 + C2);
    const u64 two2  = pk2(2.f, 2.f);
    const u64 n2_2  = pk2(-2.f, -2.f);
    const u64 n1_2  = pk2(-1.f, -1.f);

    // 11-row ring buffers of horizontally-blurred channels (registers)
    u64 rP[11], rG[11], rS[11], rX[11];
    u64 acc0 = 0ull, acc1 = 0ull;

    const int cm = cx + lane - 5;            // main col (tile idx = lane)
    const int ch = cx + 27 + lane;           // halo col (tile idx = 32+lane, lane<10)
    const bool cm_in = ((unsigned)cm < IMG);
    const bool ch_in = ((unsigned)ch < IMG);
    const int cmc = cm_in ? cm : 0;          // clamped (sz=0 masks the read)
    const int chc = ch_in ? ch : 0;

    const unsigned swbase =
        (unsigned)__cvta_generic_to_shared(&sw[wpid][0][0][0]);

    // copy one input row T into stage STG (row slot T&1)
    #define CPROW(T, STG)                                                       \
        {                                                                       \
            const int yin = ry0 - 5 + (T);                                      \
            const bool rok = ((unsigned)yin < IMG);                             \
            const int yb = (rok ? yin : 0) * IMG;                               \
            const unsigned db = swbase + (unsigned)(STG) * (2 * WCOLS * 16)     \
                              + ((T) & 1) * (WCOLS * 16) + lane * 16;           \
            const unsigned szm = (rok && cm_in) ? 4u : 0u;                      \
            const int om = yb + cmc;                                            \
            CPA(db + 0,  p0 + om, szm);  CPA(db + 4,  p1 + om, szm);            \
            CPA(db + 8,  g0 + om, szm);  CPA(db + 12, g1 + om, szm);            \
            if (lane < 10) {                                                    \
                const unsigned szh = (rok && ch_in) ? 4u : 0u;                  \
                const int oh = yb + chc;                                        \
                const unsigned dh = db + 32 * 16;                               \
                CPA(dh + 0,  p0 + oh, szh);  CPA(dh + 4,  p1 + oh, szh);        \
                CPA(dh + 8,  g0 + oh, szh);  CPA(dh + 12, g1 + oh, szh);        \
            }                                                                   \
        }
    #define CPPAIR(P) { CPROW(2 * (P), (P) & 3) CPROW(2 * (P) + 1, (P) & 3) }

    // prologue: stages 0..2 in flight (groups 0,1,2)
    CPPAIR(0) CP_COMMIT();
    CPPAIR(1) CP_COMMIT();
    CPPAIR(2) CP_COMMIT();

    for (int outer = 0; outer < 4; ++outer) {
        #pragma unroll
        for (int j = 0; j < 11; ++j) {
            const int pair = outer * 11 + j;
            if (pair < NPAIR) {
                // group(pair) complete when <=2 groups pending (one group is
                // committed EVERY iteration, empty in the tail, so the
                // invariant pending <= {pair, pair+1, pair+2} always holds)
                CP_WAIT2();
                __syncwarp();
                // issue pair+3 into stage (pair+3)&3 == (pair-1)&3 (its
                // readers finished last iteration, ordered by the syncwarp)
                if (pair + 3 < NPAIR) CPPAIR(pair + 3)
                CP_COMMIT();

                const int stg = pair & 3;
                const float4* T0 = &sw[wpid][stg][0][0];
                const float4* T1 = &sw[wpid][stg][1][0];

                const int k0 = (2 * j) % 11;
                const int k1 = (2 * j + 1) % 11;
                #define HBLUR(TP, KD)                                                       \
                    {                                                                       \
                        const float4* V = (TP) + lane;                                      \
                        float4 cv = V[5];                                                   \
                        u64 pc = pk2(cv.x, cv.y), gc = pk2(cv.z, cv.w);                     \
                        u64 hP = f2mul(pc, w2[0]);                                          \
                        u64 hG = f2mul(gc, w2[0]);                                          \
                        u64 hS = f2mul(f2fma(gc, gc, f2mul(pc, pc)), w2[0]);                \
                        u64 hX = f2mul(f2mul(pc, gc), w2[0]);                               \
                        _Pragma("unroll")                                                   \
                        for (int d = 1; d <= 5; ++d) {                                      \
                            float4 Lv = V[5 - d], Rv = V[5 + d];                            \
                            u64 pl = pk2(Lv.x, Lv.y), gl = pk2(Lv.z, Lv.w);                 \
                            u64 pr = pk2(Rv.x, Rv.y), gr = pk2(Rv.z, Rv.w);                 \
                            hP = f2fma(f2add(pl, pr), w2[d], hP);                           \
                            hG = f2fma(f2add(gl, gr), w2[d], hG);                           \
                            u64 ss = f2fma(pr, pr, f2mul(pl, pl));                          \
                            ss = f2fma(gl, gl, ss);                                         \
                            ss = f2fma(gr, gr, ss);                                         \
                            hS = f2fma(ss, w2[d], hS);                                      \
                            hX = f2fma(f2fma(pr, gr, f2mul(pl, gl)), w2[d], hX);            \
                        }                                                                   \
                        rP[KD] = hP; rG[KD] = hG; rS[KD] = hS; rX[KD] = hX;                 \
                    }
                HBLUR(T0, k0)
                HBLUR(T1, k1)
                #undef HBLUR

                if (pair >= 5) {
                    #define VS(K, JJ) (((K) + 6 + (JJ) + 11) % 11)
                    #define VBLUR(dst, r, K)                                           \
                        { u64 pa = f2fma(f2add(r[VS(K,-1)], r[VS(K,1)]), w2[1],        \
                                         f2mul(r[VS(K,0)], w2[0]));                    \
                          pa = f2fma(f2add(r[VS(K,-3)], r[VS(K,3)]), w2[3], pa);       \
                          u64 pb = f2mul(f2add(r[VS(K,-2)], r[VS(K,2)]), w2[2]);       \
                          pb = f2fma(f2add(r[VS(K,-4)], r[VS(K,4)]), w2[4], pb);       \
                          pb = f2fma(f2add(r[VS(K,-5)], r[VS(K,5)]), w2[5], pb);       \
                          dst = f2add(pa, pb); }
                    #define SSIMROW(K, ACC)                                            \
                        { u64 m1, m2, sS, s12;                                         \
                          VBLUR(m1,  rP, K); VBLUR(m2,  rG, K);                        \
                          VBLUR(sS,  rS, K); VBLUR(s12, rX, K);                        \
                          u64 m12 = f2mul(m1, m2);                                     \
                          u64 A  = f2fma(m12, two2, c1_2);                             \
                          u64 B  = f2fma(s12, two2, f2fma(m12, n2_2, c2_2));           \
                          u64 Cq = f2fma(m2, m2, f2fma(m1, m1, c1_2));                 \
                          u64 Dq = f2fma(Cq, n1_2, f2add(sS, c12_2));                  \
                          u64 num = f2mul(A, B);                                       \
                          u64 den = f2mul(Cq, Dq);                                     \
                          float na, nb, da, db;                                        \
                          unpk2(num, na, nb); unpk2(den, da, db);                      \
                          ACC = f2add(ACC, pk2(__fdividef(na, da),                     \
                                               __fdividef(nb, db))); }
                    SSIMROW(k0, acc0)
                    SSIMROW(k1, acc1)
                    #undef SSIMROW
                    #undef VBLUR
                    #undef VS
                }
            }
        }
    }
    #undef CPPAIR
    #undef CPROW

    // ---- block reduction (deterministic partials, no float atomics) ----
    u64 accT = f2add(acc0, acc1);
    float a0, a1; unpk2(accT, a0, a1);
    float s = a0 + a1;
    #pragma unroll
    for (int o = 16; o > 0; o >>= 1) s += __shfl_xor_sync(0xffffffffu, s, o);
    if (lane == 0) wred[wpid] = s;
    __syncthreads();
    if (tid == 0) {
        double bs = 0.0;
        #pragma unroll
        for (int i = 0; i < TX / 32; ++i) bs += (double)wred[i];
        const int bid = blockIdx.x + GX * (blockIdx.y + GY * blockIdx.z);
        g_part[bid] = bs;
        __threadfence();
        int old = atomicAdd(&g_cnt, 1);
        slast = (old == NBLK - 1) ? 1 : 0;
    }
    __syncthreads();

    // ---- last block finalizes (deterministic fixed-order double sum) ----
    if (slast) {
        __threadfence();
        double v = 0.0;
        #pragma unroll
        for (int i = 0; i < NBLK / TX; ++i)
            v += g_part[tid + i * TX];
        #pragma unroll
        for (int o = 16; o > 0; o >>= 1) v += __shfl_xor_sync(0xffffffffu, v, o);
        __shared__ double sh[TX / 32];
        if ((tid & 31) == 0) sh[tid >> 5] = v;
        __syncthreads();
        if (tid == 0) {
            double tot = 0.0;
            #pragma unroll
            for (int i = 0; i < TX / 32; ++i) tot += sh[i];
            out[0] = (float)(1.0 - tot / ((double)NIMG * (double)PIX));
            g_cnt = 0;   // self-reset for graph replay
        }
    }
}

extern "C" void kernel_launch(void* const* d_in, const int* in_sizes, int n_in,
                              void* d_out, int out_size)
{
    const float* pred = (const float*)d_in[0];
    const float* gt   = (const float*)d_in[1];
    float* out = (float*)d_out;

    dim3 grid(GX, GY, GZ);
    ssim_main<<<grid, TX>>>(pred, gt, out);
}

// round 16
// speedup vs baseline: 1.0717x; 1.0717x over previous
#include <cuda_runtime.h>
#include <math.h>

#define IMG   512
#define PIX   (IMG * IMG)
#define NIMG  64
#define TX    128
#define RPB   64
#define NITER (RPB + 10)            // 74 streamed rows per block
#define NPAIR (NITER / 2)           // 37 row pairs
#define WCOLS 44                    // 42 used + pad
#define GX    (IMG / TX)            // 4
#define GY    (IMG / RPB)           // 8
#define GZ    (NIMG / 2)            // 32 image pairs (f32x2 packing)
#define NBLK  (GX * GY * GZ)        // 1024

typedef unsigned long long u64;

__device__ double g_part[NBLK];
__device__ int    g_cnt;            // zero-initialized; self-resets each launch

static __device__ __forceinline__ u64 pk2(float a, float b) {
    u64 r; asm("mov.b64 %0, {%1, %2};" : "=l"(r) : "f"(a), "f"(b)); return r;
}
static __device__ __forceinline__ void unpk2(u64 v, float& a, float& b) {
    asm("mov.b64 {%0, %1}, %2;" : "=f"(a), "=f"(b) : "l"(v));
}
static __device__ __forceinline__ u64 f2add(u64 a, u64 b) {
    u64 d; asm("add.rn.f32x2 %0, %1, %2;" : "=l"(d) : "l"(a), "l"(b)); return d;
}
static __device__ __forceinline__ u64 f2sub(u64 a, u64 b) {
    u64 d; asm("sub.rn.f32x2 %0, %1, %2;" : "=l"(d) : "l"(a), "l"(b)); return d;
}
static __device__ __forceinline__ u64 f2mul(u64 a, u64 b) {
    u64 d; asm("mul.rn.f32x2 %0, %1, %2;" : "=l"(d) : "l"(a), "l"(b)); return d;
}
static __device__ __forceinline__ u64 f2fma(u64 a, u64 b, u64 c) {
    u64 d; asm("fma.rn.f32x2 %0, %1, %2, %3;" : "=l"(d) : "l"(a), "l"(b), "l"(c)); return d;
}

__global__ void __launch_bounds__(TX, 3) ssim_main(
    const float* __restrict__ pred, const float* __restrict__ gt,
    float* __restrict__ out)
{
    // R13 (U/V transform at STS, warp-private tiles, gather vblur) with a
    // SOFTWARE-PIPELINED CONSUME: each pair's vblur+SSIM runs at the TOP of
    // the NEXT iteration, in front of the STS/LDG/syncwarp stall cluster.
    // Safe: the consume reads the ring before the next hblur overwrites its
    // two slots; prev-pair ring indices stay compile-time under the unroll.
    __shared__ float4 sw[TX / 32][2][2][WCOLS];   // [warp][buf][row][col]
    __shared__ float wred[TX / 32];
    __shared__ int   slast;

    const int tid  = threadIdx.x;
    const int wpid = tid >> 5;
    const int lane = tid & 31;
    const int cx   = blockIdx.x * TX + wpid * 32;   // warp's first output col
    const int ry0  = blockIdx.y * RPB;
    const int im0  = blockIdx.z;

    const float* p0 = pred + (size_t)im0 * PIX;
    const float* p1 = pred + (size_t)(im0 + NIMG / 2) * PIX;
    const float* g0 = gt   + (size_t)im0 * PIX;
    const float* g1 = gt   + (size_t)(im0 + NIMG / 2) * PIX;

    // Gaussian 1D weights (sigma = 11/6, normalized) — same math as reference
    float w[6];
    {
        const float sig = 11.0f / 6.0f;
        const float inv = 1.0f / (2.0f * sig * sig);
        float e[6];
        #pragma unroll
        for (int d = 0; d < 6; ++d) e[d] = expf(-(float)(d * d) * inv);
        float s = e[0] + 2.f * (e[1] + e[2] + e[3] + e[4] + e[5]);
        #pragma unroll
        for (int d = 0; d < 6; ++d) w[d] = e[d] / s;
    }
    u64 w2[6];
    #pragma unroll
    for (int d = 0; d < 6; ++d) w2[d] = pk2(w[d], w[d]);

    const float C1 = 0.01f * 0.01f;
    const float C2 = 0.03f * 0.03f;
    const u64 c1_2  = pk2(C1, C1);
    const u64 c2_2  = pk2(C2, C2);
    const u64 half2 = pk2(0.5f, 0.5f);

    // 11-row ring buffers of horizontally-blurred channels (registers)
    u64 rU[11], rV[11], rUU[11], rVV[11];
    u64 acc0 = 0ull, acc1 = 0ull;

    const int cmain = cx + lane - 5;         // cols cx-5 .. cx+26
    const int chalo = cx + 27 + lane;        // cols cx+27 .. cx+36 (lane<10)
    const bool cm_in = ((unsigned)cmain < IMG);
    const bool ch_in = ((unsigned)chalo < IMG) && (lane < 10);

    // prefetch register sets: RAW p/g values
    float pmA0, pmA1, gmA0, gmA1, phA0, phA1, ghA0, ghA1;
    float pmB0, pmB1, gmB0, gmB1, phB0, phB1, ghB0, ghB1;

    #define LOADROW(sfx, T)                                                     \
        {                                                                       \
            const int yin = ry0 - 5 + (T);                                      \
            const bool rok = ((unsigned)yin < IMG);                             \
            const bool ok  = rok && cm_in;                                      \
            const int off = yin * IMG + cmain;                                  \
            pm##sfx##0 = ok ? p0[off] : 0.f;  pm##sfx##1 = ok ? p1[off] : 0.f;  \
            gm##sfx##0 = ok ? g0[off] : 0.f;  gm##sfx##1 = ok ? g1[off] : 0.f;  \
            const bool ok2 = rok && ch_in;                                      \
            const int off2 = yin * IMG + chalo;                                 \
            ph##sfx##0 = ok2 ? p0[off2] : 0.f; ph##sfx##1 = ok2 ? p1[off2] : 0.f;\
            gh##sfx##0 = ok2 ? g0[off2] : 0.f; gh##sfx##1 = ok2 ? g1[off2] : 0.f;\
        }

    LOADROW(A, 0)
    LOADROW(B, 1)

    #define VS(K, JJ) (((K) + 6 + (JJ) + 11) % 11)
    #define VBLUR(dst, r, K)                                           \
        { u64 pa = f2fma(f2add(r[VS(K,-1)], r[VS(K,1)]), w2[1],        \
                         f2mul(r[VS(K,0)], w2[0]));                    \
          pa = f2fma(f2add(r[VS(K,-3)], r[VS(K,3)]), w2[3], pa);       \
          u64 pb = f2mul(f2add(r[VS(K,-2)], r[VS(K,2)]), w2[2]);       \
          pb = f2fma(f2add(r[VS(K,-4)], r[VS(K,4)]), w2[4], pb);       \
          pb = f2fma(f2add(r[VS(K,-5)], r[VS(K,5)]), w2[5], pb);       \
          dst = f2add(pa, pb); }
    #define SSIMROW(K, ACC)                                            \
        { u64 mU, mV, SU, SV;                                          \
          VBLUR(mU, rU,  K); VBLUR(mV, rV,  K);                        \
          VBLUR(SU, rUU, K); VBLUR(SV, rVV, K);                        \
          u64 t1 = f2mul(mU, mU);                                      \
          u64 t2 = f2mul(mV, mV);                                      \
          u64 dm = f2sub(t1, t2);          /* 4 m1 m2 */               \
          u64 sm = f2add(t1, t2);          /* 2(m1^2+m2^2) */          \
          t1 = f2fma(dm, half2, c1_2);     /* A  */                    \
          t2 = f2fma(f2sub(f2sub(SU, SV), dm), half2, c2_2); /* B */   \
          u64 num = f2mul(t1, t2);                                     \
          t1 = f2fma(sm, half2, c1_2);     /* Cq */                    \
          t2 = f2fma(f2sub(f2add(SU, SV), sm), half2, c2_2); /* Dq */  \
          u64 den = f2mul(t1, t2);                                     \
          float na, nb, da, db;                                        \
          unpk2(num, na, nb); unpk2(den, da, db);                      \
          ACC = f2add(ACC, pk2(__fdividef(na, da),                     \
                               __fdividef(nb, db))); }

    for (int outer = 0; outer < 4; ++outer) {
        #pragma unroll
        for (int j = 0; j < 11; ++j) {
            const int pair = outer * 11 + j;
            if (pair < NPAIR) {
                const int buf = pair & 1;
                // ---- pipelined consume of the PREVIOUS pair (independent
                //      fma block filling the STS/LDG/syncwarp stall window).
                //      prev pair's ring rows: k0p=(2j+20)%11, k1p=(2j+21)%11
                const int k0p = (2 * j + 20) % 11;
                const int k1p = (2 * j + 21) % 11;
                if (pair >= 6) {
                    SSIMROW(k0p, acc0)
                    SSIMROW(k1p, acc1)
                }
                // ---- store both rows, U/V transform transient at STS ----
                sw[wpid][buf][0][lane] = make_float4(pmA0 + gmA0, pmA1 + gmA1,
                                                     pmA0 - gmA0, pmA1 - gmA1);
                sw[wpid][buf][1][lane] = make_float4(pmB0 + gmB0, pmB1 + gmB1,
                                                     pmB0 - gmB0, pmB1 - gmB1);
                if (lane < 10) {
                    sw[wpid][buf][0][32 + lane] = make_float4(phA0 + ghA0, phA1 + ghA1,
                                                              phA0 - ghA0, phA1 - ghA1);
                    sw[wpid][buf][1][32 + lane] = make_float4(phB0 + ghB0, phB1 + ghB1,
                                                              phB0 - ghB0, phB1 - ghB1);
                }
                // ---- prefetch next pair (warp-local; no block barrier) ----
                const int t0 = 2 * pair;
                if (t0 + 2 < NITER) LOADROW(A, t0 + 2)
                if (t0 + 3 < NITER) LOADROW(B, t0 + 3)
                __syncwarp();

                const int k0 = (2 * j) % 11;
                const int k1 = (2 * j + 1) % 11;
                #define HBLUR(ROW, KD)                                                      \
                    {                                                                       \
                        const float4* Vv = &sw[wpid][buf][ROW][lane];                       \
                        float4 cv = Vv[5];                                                  \
                        u64 uc = pk2(cv.x, cv.y), vc = pk2(cv.z, cv.w);                     \
                        u64 hU  = f2mul(uc, w2[0]);                                         \
                        u64 hV  = f2mul(vc, w2[0]);                                         \
                        u64 hUU = f2mul(f2mul(uc, uc), w2[0]);                              \
                        u64 hVV = f2mul(f2mul(vc, vc), w2[0]);                              \
                        _Pragma("unroll")                                                   \
                        for (int d = 1; d <= 5; ++d) {                                      \
                            float4 Lv = Vv[5 - d], Rv = Vv[5 + d];                          \
                            u64 ul = pk2(Lv.x, Lv.y), vl = pk2(Lv.z, Lv.w);                 \
                            u64 ur = pk2(Rv.x, Rv.y), vr = pk2(Rv.z, Rv.w);                 \
                            hU  = f2fma(f2add(ul, ur), w2[d], hU);                          \
                            hV  = f2fma(f2add(vl, vr), w2[d], hV);                          \
                            hUU = f2fma(f2fma(ur, ur, f2mul(ul, ul)), w2[d], hUU);          \
                            hVV = f2fma(f2fma(vr, vr, f2mul(vl, vl)), w2[d], hVV);          \
                        }                                                                   \
                        rU[KD] = hU; rV[KD] = hV; rUU[KD] = hUU; rVV[KD] = hVV;             \
                    }
                HBLUR(0, k0)
                HBLUR(1, k1)
                #undef HBLUR
            }
        }
    }
    // ---- epilogue: consume the final pair (36 -> j=3: k0=6, k1=7) ----
    SSIMROW(6, acc0)
    SSIMROW(7, acc1)
    #undef SSIMROW
    #undef VBLUR
    #undef VS
    #undef LOADROW

    // ---- block reduction (deterministic partials, no float atomics) ----
    u64 accT = f2add(acc0, acc1);
    float a0, a1; unpk2(accT, a0, a1);
    float s = a0 + a1;
    #pragma unroll
    for (int o = 16; o > 0; o >>= 1) s += __shfl_xor_sync(0xffffffffu, s, o);
    if (lane == 0) wred[wpid] = s;
    __syncthreads();
    if (tid == 0) {
        double bs = 0.0;
        #pragma unroll
        for (int i = 0; i < TX / 32; ++i) bs += (double)wred[i];
        const int bid = blockIdx.x + GX * (blockIdx.y + GY * blockIdx.z);
        g_part[bid] = bs;
        __threadfence();
        int old = atomicAdd(&g_cnt, 1);
        slast = (old == NBLK - 1) ? 1 : 0;
    }
    __syncthreads();

    // ---- last block finalizes (deterministic fixed-order double sum) ----
    if (slast) {
        __threadfence();
        double v = 0.0;
        #pragma unroll
        for (int i = 0; i < NBLK / TX; ++i)
            v += g_part[tid + i * TX];
        #pragma unroll
        for (int o = 16; o > 0; o >>= 1) v += __shfl_xor_sync(0xffffffffu, v, o);
        __shared__ double sh[TX / 32];
        if ((tid & 31) == 0) sh[tid >> 5] = v;
        __syncthreads();
        if (tid == 0) {
            double tot = 0.0;
            #pragma unroll
            for (int i = 0; i < TX / 32; ++i) tot += sh[i];
            out[0] = (float)(1.0 - tot / ((double)NIMG * (double)PIX));
            g_cnt = 0;   // self-reset for graph replay
        }
    }
}

extern "C" void kernel_launch(void* const* d_in, const int* in_sizes, int n_in,
                              void* d_out, int out_size)
{
    const float* pred = (const float*)d_in[0];
    const float* gt   = (const float*)d_in[1];
    float* out = (float*)d_out;

    dim3 grid(GX, GY, GZ);
    ssim_main<<<grid, TX>>>(pred, gt, out);
}

// round 17
// speedup vs baseline: 1.1308x; 1.0551x over previous
#include <cuda_runtime.h>
#include <math.h>

#define IMG   512
#define PIX   (IMG * IMG)
#define NIMG  64
#define TX    128
#define RPB   64
#define NITER (RPB + 10)            // 74 streamed rows per block
#define NPAIR (NITER / 2)           // 37 row pairs
#define WCOLS 44                    // 42 used + pad
#define GX    (IMG / TX)            // 4
#define GY    (IMG / RPB)           // 8
#define GZ    (NIMG / 2)            // 32 image pairs (f32x2 packing)
#define NBLK  (GX * GY * GZ)        // 1024

typedef unsigned long long u64;

__device__ double g_part[NBLK];
__device__ int    g_cnt;            // zero-initialized; self-resets each launch

static __device__ __forceinline__ u64 pk2(float a, float b) {
    u64 r; asm("mov.b64 %0, {%1, %2};" : "=l"(r) : "f"(a), "f"(b)); return r;
}
static __device__ __forceinline__ void unpk2(u64 v, float& a, float& b) {
    asm("mov.b64 {%0, %1}, %2;" : "=f"(a), "=f"(b) : "l"(v));
}
static __device__ __forceinline__ u64 f2add(u64 a, u64 b) {
    u64 d; asm("add.rn.f32x2 %0, %1, %2;" : "=l"(d) : "l"(a), "l"(b)); return d;
}
static __device__ __forceinline__ u64 f2sub(u64 a, u64 b) {
    u64 d; asm("sub.rn.f32x2 %0, %1, %2;" : "=l"(d) : "l"(a), "l"(b)); return d;
}
static __device__ __forceinline__ u64 f2mul(u64 a, u64 b) {
    u64 d; asm("mul.rn.f32x2 %0, %1, %2;" : "=l"(d) : "l"(a), "l"(b)); return d;
}
static __device__ __forceinline__ u64 f2fma(u64 a, u64 b, u64 c) {
    u64 d; asm("fma.rn.f32x2 %0, %1, %2, %3;" : "=l"(d) : "l"(a), "l"(b), "l"(c)); return d;
}

__global__ void __launch_bounds__(TX, 3) ssim_main(
    const float* __restrict__ pred, const float* __restrict__ gt,
    float* __restrict__ out)
{
    // Converged design (R13):
    //  - f32x2 packing: each lane processes one column of TWO images
    //  - warp-private double-buffered tiles: NO block barrier in the main
    //    loop (only __syncwarp), warps drift out of phase across pipes
    //  - U/V transform (u=p+g, v=p-g) applied TRANSIENTLY at STS time:
    //    blur channels U, V, U^2, V^2 (minimal 4-moment set)
    //  - register ring of 11 hblurred rows; gather vblur with split chains
    //  - raw p/g prefetch registers, distance-1 pair prefetch before sync
    //  - fused deterministic reduction (last block finalizes)
    __shared__ float4 sw[TX / 32][2][2][WCOLS];   // [warp][buf][row][col]
    __shared__ float wred[TX / 32];
    __shared__ int   slast;

    const int tid  = threadIdx.x;
    const int wpid = tid >> 5;
    const int lane = tid & 31;
    const int cx   = blockIdx.x * TX + wpid * 32;   // warp's first output col
    const int ry0  = blockIdx.y * RPB;
    const int im0  = blockIdx.z;

    const float* p0 = pred + (size_t)im0 * PIX;
    const float* p1 = pred + (size_t)(im0 + NIMG / 2) * PIX;
    const float* g0 = gt   + (size_t)im0 * PIX;
    const float* g1 = gt   + (size_t)(im0 + NIMG / 2) * PIX;

    // Gaussian 1D weights (sigma = 11/6, normalized) — same math as reference
    float w[6];
    {
        const float sig = 11.0f / 6.0f;
        const float inv = 1.0f / (2.0f * sig * sig);
        float e[6];
        #pragma unroll
        for (int d = 0; d < 6; ++d) e[d] = expf(-(float)(d * d) * inv);
        float s = e[0] + 2.f * (e[1] + e[2] + e[3] + e[4] + e[5]);
        #pragma unroll
        for (int d = 0; d < 6; ++d) w[d] = e[d] / s;
    }
    u64 w2[6];
    #pragma unroll
    for (int d = 0; d < 6; ++d) w2[d] = pk2(w[d], w[d]);

    const float C1 = 0.01f * 0.01f;
    const float C2 = 0.03f * 0.03f;
    const u64 c1_2  = pk2(C1, C1);
    const u64 c2_2  = pk2(C2, C2);
    const u64 half2 = pk2(0.5f, 0.5f);

    // 11-row ring buffers of horizontally-blurred channels (registers)
    u64 rU[11], rV[11], rUU[11], rVV[11];
    u64 acc0 = 0ull, acc1 = 0ull;

    const int cmain = cx + lane - 5;         // cols cx-5 .. cx+26
    const int chalo = cx + 27 + lane;        // cols cx+27 .. cx+36 (lane<10)
    const bool cm_in = ((unsigned)cmain < IMG);
    const bool ch_in = ((unsigned)chalo < IMG) && (lane < 10);

    // prefetch register sets: RAW p/g values
    float pmA0, pmA1, gmA0, gmA1, phA0, phA1, ghA0, ghA1;
    float pmB0, pmB1, gmB0, gmB1, phB0, phB1, ghB0, ghB1;

    #define LOADROW(sfx, T)                                                     \
        {                                                                       \
            const int yin = ry0 - 5 + (T);                                      \
            const bool rok = ((unsigned)yin < IMG);                             \
            const bool ok  = rok && cm_in;                                      \
            const int off = yin * IMG + cmain;                                  \
            pm##sfx##0 = ok ? p0[off] : 0.f;  pm##sfx##1 = ok ? p1[off] : 0.f;  \
            gm##sfx##0 = ok ? g0[off] : 0.f;  gm##sfx##1 = ok ? g1[off] : 0.f;  \
            const bool ok2 = rok && ch_in;                                      \
            const int off2 = yin * IMG + chalo;                                 \
            ph##sfx##0 = ok2 ? p0[off2] : 0.f; ph##sfx##1 = ok2 ? p1[off2] : 0.f;\
            gh##sfx##0 = ok2 ? g0[off2] : 0.f; gh##sfx##1 = ok2 ? g1[off2] : 0.f;\
        }

    LOADROW(A, 0)
    LOADROW(B, 1)

    for (int outer = 0; outer < 4; ++outer) {
        #pragma unroll
        for (int j = 0; j < 11; ++j) {
            const int pair = outer * 11 + j;
            if (pair < NPAIR) {
                const int buf = pair & 1;
                // ---- store both rows, transformed TRANSIENTLY at STS ----
                sw[wpid][buf][0][lane] = make_float4(pmA0 + gmA0, pmA1 + gmA1,
                                                     pmA0 - gmA0, pmA1 - gmA1);
                sw[wpid][buf][1][lane] = make_float4(pmB0 + gmB0, pmB1 + gmB1,
                                                     pmB0 - gmB0, pmB1 - gmB1);
                if (lane < 10) {
                    sw[wpid][buf][0][32 + lane] = make_float4(phA0 + ghA0, phA1 + ghA1,
                                                              phA0 - ghA0, phA1 - ghA1);
                    sw[wpid][buf][1][32 + lane] = make_float4(phB0 + ghB0, phB1 + ghB1,
                                                              phB0 - ghB0, phB1 - ghB1);
                }
                // ---- prefetch next pair (warp-local; no block barrier) ----
                const int t0 = 2 * pair;
                if (t0 + 2 < NITER) LOADROW(A, t0 + 2)
                if (t0 + 3 < NITER) LOADROW(B, t0 + 3)
                __syncwarp();

                const int k0 = (2 * j) % 11;
                const int k1 = (2 * j + 1) % 11;
                #define HBLUR(ROW, KD)                                                      \
                    {                                                                       \
                        const float4* Vv = &sw[wpid][buf][ROW][lane];                       \
                        float4 cv = Vv[5];                                                  \
                        u64 uc = pk2(cv.x, cv.y), vc = pk2(cv.z, cv.w);                     \
                        u64 hU  = f2mul(uc, w2[0]);                                         \
                        u64 hV  = f2mul(vc, w2[0]);                                         \
                        u64 hUU = f2mul(f2mul(uc, uc), w2[0]);                              \
                        u64 hVV = f2mul(f2mul(vc, vc), w2[0]);                              \
                        _Pragma("unroll")                                                   \
                        for (int d = 1; d <= 5; ++d) {                                      \
                            float4 Lv = Vv[5 - d], Rv = Vv[5 + d];                          \
                            u64 ul = pk2(Lv.x, Lv.y), vl = pk2(Lv.z, Lv.w);                 \
                            u64 ur = pk2(Rv.x, Rv.y), vr = pk2(Rv.z, Rv.w);                 \
                            hU  = f2fma(f2add(ul, ur), w2[d], hU);                          \
                            hV  = f2fma(f2add(vl, vr), w2[d], hV);                          \
                            hUU = f2fma(f2fma(ur, ur, f2mul(ul, ul)), w2[d], hUU);          \
                            hVV = f2fma(f2fma(vr, vr, f2mul(vl, vl)), w2[d], hVV);          \
                        }                                                                   \
                        rU[KD] = hU; rV[KD] = hV; rUU[KD] = hUU; rVV[KD] = hVV;             \
                    }
                HBLUR(0, k0)
                HBLUR(1, k1)
                #undef HBLUR

                if (pair >= 5) {
                    #define VS(K, JJ) (((K) + 6 + (JJ) + 11) % 11)
                    #define VBLUR(dst, r, K)                                           \
                        { u64 pa = f2fma(f2add(r[VS(K,-1)], r[VS(K,1)]), w2[1],        \
                                         f2mul(r[VS(K,0)], w2[0]));                    \
                          pa = f2fma(f2add(r[VS(K,-3)], r[VS(K,3)]), w2[3], pa);       \
                          u64 pb = f2mul(f2add(r[VS(K,-2)], r[VS(K,2)]), w2[2]);       \
                          pb = f2fma(f2add(r[VS(K,-4)], r[VS(K,4)]), w2[4], pb);       \
                          pb = f2fma(f2add(r[VS(K,-5)], r[VS(K,5)]), w2[5], pb);       \
                          dst = f2add(pa, pb); }
                    // tight epilogue: reuse temps to cap live u64 count
                    #define SSIMROW(K, ACC)                                            \
                        { u64 mU, mV, SU, SV;                                          \
                          VBLUR(mU, rU,  K); VBLUR(mV, rV,  K);                        \
                          VBLUR(SU, rUU, K); VBLUR(SV, rVV, K);                        \
                          u64 t1 = f2mul(mU, mU);                                      \
                          u64 t2 = f2mul(mV, mV);                                      \
                          u64 dm = f2sub(t1, t2);          /* 4 m1 m2 */               \
                          u64 sm = f2add(t1, t2);          /* 2(m1^2+m2^2) */          \
                          t1 = f2fma(dm, half2, c1_2);     /* A  */                    \
                          t2 = f2fma(f2sub(f2sub(SU, SV), dm), half2, c2_2); /* B */   \
                          u64 num = f2mul(t1, t2);                                     \
                          t1 = f2fma(sm, half2, c1_2);     /* Cq */                    \
                          t2 = f2fma(f2sub(f2add(SU, SV), sm), half2, c2_2); /* Dq */  \
                          u64 den = f2mul(t1, t2);                                     \
                          float na, nb, da, db;                                        \
                          unpk2(num, na, nb); unpk2(den, da, db);                      \
                          ACC = f2add(ACC, pk2(__fdividef(na, da),                     \
                                               __fdividef(nb, db))); }
                    SSIMROW(k0, acc0)
                    SSIMROW(k1, acc1)
                    #undef SSIMROW
                    #undef VBLUR
                    #undef VS
                }
            }
        }
    }
    #undef LOADROW

    // ---- block reduction (deterministic partials, no float atomics) ----
    u64 accT = f2add(acc0, acc1);
    float a0, a1; unpk2(accT, a0, a1);
    float s = a0 + a1;
    #pragma unroll
    for (int o = 16; o > 0; o >>= 1) s += __shfl_xor_sync(0xffffffffu, s, o);
    if (lane == 0) wred[wpid] = s;
    __syncthreads();
    if (tid == 0) {
        double bs = 0.0;
        #pragma unroll
        for (int i = 0; i < TX / 32; ++i) bs += (double)wred[i];
        const int bid = blockIdx.x + GX * (blockIdx.y + GY * blockIdx.z);
        g_part[bid] = bs;
        __threadfence();
        int old = atomicAdd(&g_cnt, 1);
        slast = (old == NBLK - 1) ? 1 : 0;
    }
    __syncthreads();

    // ---- last block finalizes (deterministic fixed-order double sum) ----
    if (slast) {
        __threadfence();
        double v = 0.0;
        #pragma unroll
        for (int i = 0; i < NBLK / TX; ++i)
            v += g_part[tid + i * TX];
        #pragma unroll
        for (int o = 16; o > 0; o >>= 1) v += __shfl_xor_sync(0xffffffffu, v, o);
        __shared__ double sh[TX / 32];
        if ((tid & 31) == 0) sh[tid >> 5] = v;
        __syncthreads();
        if (tid == 0) {
            double tot = 0.0;
            #pragma unroll
            for (int i = 0; i < TX / 32; ++i) tot += sh[i];
            out[0] = (float)(1.0 - tot / ((double)NIMG * (double)PIX));
            g_cnt = 0;   // self-reset for graph replay
        }
    }
}

extern "C" void kernel_launch(void* const* d_in, const int* in_sizes, int n_in,
                              void* d_out, int out_size)
{
    const float* pred = (const float*)d_in[0];
    const float* gt   = (const float*)d_in[1];
    float* out = (float*)d_out;

    dim3 grid(GX, GY, GZ);
    ssim_main<<<grid, TX>>>(pred, gt, out);
}